// round 15
// baseline (speedup 1.0000x reference)
#include <cuda_runtime.h>

// Residual VQ via 3xTF32 tensor-core MMA (mma.sync.m16n8k8, mask split).
// hi = x & 0xFFFFE000 (exactly tf32), lo = x - hi (exact fp32, HW-truncated).
// Term-major MMA order (accumulator reuse distance 8).
// NEW (R15): next stage's codebook is prefetched into the B tile with
// cp.async.cg right after the post-epilogue barrier, overlapping its global
// latency with merge/rescue/update; rescue+update read the exact fp32
// codebook from global (L2-resident). cnorm recomputed from SMEM with the
// identical summation order -> decisions bitwise unchanged.
// Rescue: fp64 full rescan when top-2 gap < 2e-3, 4-way ILP DFMA chains.
// Output (float32): x_q [N*128], mean_loss [1], indices [N*S].

#define D        128
#define C        256
#define ROWS     128
#define THREADS  1024
#define NWARP    32
#define MAXGRID  4096
#define EPS_GAP  2e-3f
#define LDA      132            // padded row stride (floats)

__device__ float        g_part[MAXGRID];
__device__ unsigned int g_cnt = 0;

// dynamic smem (floats)
#define OFF_A    0
#define OFF_B    (OFF_A + ROWS*LDA)
#define OFF_CN   (OFF_B + C*LDA)
#define OFF_PB1  (OFF_CN + 256)
#define OFF_PB2  (OFF_PB1 + 1024)
#define OFF_PI1  (OFF_PB2 + 1024)
#define OFF_IDX  (OFF_PI1 + 1024)
#define OFF_IALL (OFF_IDX + 128)
#define OFF_RED  (OFF_IALL + 128*8)
#define OFF_CNT  (OFF_RED + 32)
#define OFF_LIST (OFF_CNT + 1)
#define SMEM_FLOATS (OFF_LIST + 128)
#define SMEM_BYTES  (SMEM_FLOATS * 4 + 64)

#define MMA_TF32(c0,c1,c2,c3,a0,a1,a2,a3,b0,b1) \
    asm volatile("mma.sync.aligned.m16n8k8.row.col.f32.tf32.tf32.f32 " \
                 "{%0,%1,%2,%3},{%4,%5,%6,%7},{%8,%9},{%0,%1,%2,%3};" \
                 : "+f"(c0), "+f"(c1), "+f"(c2), "+f"(c3) \
                 : "r"(a0), "r"(a1), "r"(a2), "r"(a3), "r"(b0), "r"(b1))

__device__ __forceinline__ void split_tf32(float x, unsigned& hi, unsigned& lo) {
    hi = __float_as_uint(x) & 0xFFFFE000u;
    lo = __float_as_uint(x - __uint_as_float(hi));
}

__device__ __forceinline__ void cp_async16(void* smem_dst, const void* gmem_src) {
    const unsigned sa = (unsigned)__cvta_generic_to_shared(smem_dst);
    asm volatile("cp.async.cg.shared.global [%0], [%1], 16;"
                 :: "r"(sa), "l"(gmem_src) : "memory");
}

__global__ void __launch_bounds__(THREADS, 1)
rvq_kernel(const float* __restrict__ x, const float* __restrict__ cbs,
           float* __restrict__ out, int N, int S)
{
    extern __shared__ float sm[];
    float* A       = sm + OFF_A;            // residual [row][k], stride 132
    float* B       = sm + OFF_B;            // codebook [code][k], stride 132
    float* cnorm   = sm + OFF_CN;
    float* pB1     = sm + OFF_PB1;          // partial best  [row*8 + ct]
    float* pB2     = sm + OFF_PB2;          // partial 2nd   [row*8 + ct]
    int*   pI1     = (int*)(sm + OFF_PI1);  // partial index [row*8 + ct]
    int*   sIdx    = (int*)(sm + OFF_IDX);
    float* sIdxAll = sm + OFF_IALL;
    float* sRed    = sm + OFF_RED;
    int*   sCnt    = (int*)(sm + OFF_CNT);
    int*   sList   = (int*)(sm + OFF_LIST);
    __shared__ int sLast;

    const int tid  = threadIdx.x;
    const int lane = tid & 31;
    const int w    = tid >> 5;       // 0..31
    const int g    = lane >> 2;      // mma group (0..7)
    const int t    = lane & 3;       // thread-in-group (0..3)
    const long long rowBase = (long long)blockIdx.x * ROWS;

    const int rt = w & 3;            // row tile: rows [rt*32, rt*32+32)
    const int ct = w >> 2;           // code tile: codes [ct*32, ct*32+32)
    const int arow = rt * 32 + g;
    const int r8 = lane >> 3, f = lane & 7;

    // ---- prefetch stage-0 codebook into B (cp.async), overlap with x load ----
    #pragma unroll
    for (int i = 0; i < 2; ++i) {
        const int code = 8 * w + 4 * i + r8;
        #pragma unroll
        for (int j = 0; j < 4; ++j) {
            const int k = j * 32 + f * 4;
            cp_async16(B + code * LDA + k, cbs + code * D + k);
        }
    }
    asm volatile("cp.async.commit_group;" ::: "memory");

    // ---- load x tile into A: warp w -> rows [4w, 4w+4) ----
    {
        const int row = 4 * w + r8;
        #pragma unroll
        for (int j = 0; j < 4; ++j) {
            const int k = j * 32 + f * 4;
            *(float4*)(A + row * LDA + k) =
                *(const float4*)(x + (rowBase + row) * D + k);
        }
    }

    // ---- wait for B, compute cnorm (fixed order: j-major, shuffle tree) ----
    asm volatile("cp.async.wait_group 0;" ::: "memory");
    __syncthreads();
    #pragma unroll
    for (int i = 0; i < 2; ++i) {
        const int code = 8 * w + 4 * i + r8;
        float psum = 0.f;
        #pragma unroll
        for (int j = 0; j < 4; ++j) {
            const int k = j * 32 + f * 4;
            const float4 v = *(const float4*)(B + code * LDA + k);
            psum += v.x * v.x + v.y * v.y + v.z * v.z + v.w * v.w;
        }
        psum += __shfl_down_sync(0xffffffffu, psum, 4);
        psum += __shfl_down_sync(0xffffffffu, psum, 2);
        psum += __shfl_down_sync(0xffffffffu, psum, 1);
        if (f == 0) cnorm[code] = psum;
    }

    float lsum = 0.f;

    for (int s = 0; s < S; ++s) {
        const float* cbS = cbs + (size_t)s * C * D;
        __syncthreads();             // B, cnorm, A(updated) ready for stage s
        if (tid == 0) *sCnt = 0;

        // ---- 3xTF32 MMA, term-major issue order, B loaded raw once per kt ----
        float acc[2][4][4];
        #pragma unroll
        for (int h = 0; h < 2; ++h)
            #pragma unroll
            for (int n = 0; n < 4; ++n)
                #pragma unroll
                for (int q = 0; q < 4; ++q) acc[h][n][q] = 0.f;

        #pragma unroll 2
        for (int kt = 0; kt < 16; ++kt) {
            const int kb = kt * 8;
            unsigned afh[2][4], afl[2][4];
            #pragma unroll
            for (int h = 0; h < 2; ++h) {
                const int r0 = arow + 16 * h;
                split_tf32(A[ r0      * LDA + kb + t],     afh[h][0], afl[h][0]);
                split_tf32(A[(r0 + 8) * LDA + kb + t],     afh[h][1], afl[h][1]);
                split_tf32(A[ r0      * LDA + kb + t + 4], afh[h][2], afl[h][2]);
                split_tf32(A[(r0 + 8) * LDA + kb + t + 4], afh[h][3], afl[h][3]);
            }
            unsigned braw[4][2];
            #pragma unroll
            for (int n = 0; n < 4; ++n) {
                const int code = ct * 32 + n * 8 + g;
                braw[n][0] = __float_as_uint(B[code * LDA + kb + t]);
                braw[n][1] = __float_as_uint(B[code * LDA + kb + t + 4]);
            }
            // term 0: Ahi x Bhi
            #pragma unroll
            for (int n = 0; n < 4; ++n) {
                const unsigned b0 = braw[n][0] & 0xFFFFE000u;
                const unsigned b1 = braw[n][1] & 0xFFFFE000u;
                MMA_TF32(acc[0][n][0], acc[0][n][1], acc[0][n][2], acc[0][n][3],
                         afh[0][0], afh[0][1], afh[0][2], afh[0][3], b0, b1);
                MMA_TF32(acc[1][n][0], acc[1][n][1], acc[1][n][2], acc[1][n][3],
                         afh[1][0], afh[1][1], afh[1][2], afh[1][3], b0, b1);
            }
            // term 1: Ahi x Blo
            #pragma unroll
            for (int n = 0; n < 4; ++n) {
                const unsigned h0 = braw[n][0] & 0xFFFFE000u;
                const unsigned h1 = braw[n][1] & 0xFFFFE000u;
                const unsigned bl0 = __float_as_uint(
                    __uint_as_float(braw[n][0]) - __uint_as_float(h0));
                const unsigned bl1 = __float_as_uint(
                    __uint_as_float(braw[n][1]) - __uint_as_float(h1));
                MMA_TF32(acc[0][n][0], acc[0][n][1], acc[0][n][2], acc[0][n][3],
                         afh[0][0], afh[0][1], afh[0][2], afh[0][3], bl0, bl1);
                MMA_TF32(acc[1][n][0], acc[1][n][1], acc[1][n][2], acc[1][n][3],
                         afh[1][0], afh[1][1], afh[1][2], afh[1][3], bl0, bl1);
            }
            // term 2: Alo x Bhi
            #pragma unroll
            for (int n = 0; n < 4; ++n) {
                const unsigned b0 = braw[n][0] & 0xFFFFE000u;
                const unsigned b1 = braw[n][1] & 0xFFFFE000u;
                MMA_TF32(acc[0][n][0], acc[0][n][1], acc[0][n][2], acc[0][n][3],
                         afl[0][0], afl[0][1], afl[0][2], afl[0][3], b0, b1);
                MMA_TF32(acc[1][n][0], acc[1][n][1], acc[1][n][2], acc[1][n][3],
                         afl[1][0], afl[1][1], afl[1][2], afl[1][3], b0, b1);
            }
        }

        // ---- per-(row, code-tile) top-2 partials (no B access) ----
        #pragma unroll
        for (int h = 0; h < 2; ++h) {
            #pragma unroll
            for (int rr = 0; rr < 2; ++rr) {        // row = arow + 16h + 8rr
                float b1v = 3.4e38f, b2v = 3.4e38f;
                int   i1  = 0;
                #pragma unroll
                for (int n = 0; n < 4; ++n) {
                    const int code0 = ct * 32 + n * 8 + 2 * t;
                    const float s0 = fmaf(-2.f, acc[h][n][rr * 2 + 0], cnorm[code0]);
                    const float s1 = fmaf(-2.f, acc[h][n][rr * 2 + 1], cnorm[code0 + 1]);
                    if (s0 < b1v) { b2v = b1v; b1v = s0; i1 = code0; }
                    else if (s0 < b2v) b2v = s0;
                    if (s1 < b1v) { b2v = b1v; b1v = s1; i1 = code0 + 1; }
                    else if (s1 < b2v) b2v = s1;
                }
                #pragma unroll
                for (int off = 1; off <= 2; off <<= 1) {
                    const float ov1 = __shfl_xor_sync(0xffffffffu, b1v, off);
                    const int   oi  = __shfl_xor_sync(0xffffffffu, i1, off);
                    const float ov2 = __shfl_xor_sync(0xffffffffu, b2v, off);
                    const float m2  = fminf(fmaxf(b1v, ov1), fminf(b2v, ov2));
                    if (ov1 < b1v || (ov1 == b1v && oi < i1)) { b1v = ov1; i1 = oi; }
                    b2v = m2;
                }
                if (t == 0) {
                    const int row = arow + 16 * h + 8 * rr;
                    pB1[row * 8 + ct] = b1v;
                    pB2[row * 8 + ct] = b2v;
                    pI1[row * 8 + ct] = i1;
                }
            }
        }
        __syncthreads();             // all warps done reading B for stage s

        // ---- prefetch next stage's codebook into B (overlaps next phases) ----
        if (s + 1 < S) {
            const float* cbN = cbs + (size_t)(s + 1) * C * D;
            #pragma unroll
            for (int i = 0; i < 2; ++i) {
                const int code = 8 * w + 4 * i + r8;
                #pragma unroll
                for (int j = 0; j < 4; ++j) {
                    const int k = j * 32 + f * 4;
                    cp_async16(B + code * LDA + k, cbN + code * D + k);
                }
            }
            asm volatile("cp.async.commit_group;" ::: "memory");
        }

        // ---- merge 8 code-tile partials per row; nominate fp64 rescans ----
        if (w < 4) {
            const int row = w * 32 + lane;
            float b1v = 3.4e38f, b2v = 3.4e38f;
            int   i1  = 0;
            #pragma unroll
            for (int c = 0; c < 8; ++c) {
                const float ov1 = pB1[row * 8 + c];
                const float ov2 = pB2[row * 8 + c];
                const int   oi  = pI1[row * 8 + c];
                const float m2  = fminf(fmaxf(b1v, ov1), fminf(b2v, ov2));
                if (ov1 < b1v || (ov1 == b1v && oi < i1)) { b1v = ov1; i1 = oi; }
                b2v = m2;
            }
            if (b2v - b1v < EPS_GAP) {
                const int pos = atomicAdd(sCnt, 1);
                sList[pos] = row;
            } else {
                sIdx[row] = i1;
                sIdxAll[row * 8 + s] = (float)i1;
            }
        }
        __syncthreads();

        // ---- fp64 full rescan for near-tie rows (exact fp32 from global) ----
        {
            const int cnt = *sCnt;
            for (int e = w; e < cnt; e += NWARP) {
                const int row = sList[e];
                double d1 = 1e300; int di = 0x7fffffff;
                #pragma unroll
                for (int cc = 0; cc < 8; ++cc) {
                    const int code = cc * 32 + lane;
                    const float* Bc  = cbS + code * D;
                    const float* Arf = A + row * LDA;
                    double q0 = 0.0, q1 = 0.0, q2 = 0.0, q3 = 0.0;
                    for (int k = 0; k < D; k += 4) {
                        const double f0 = (double)Arf[k]     - (double)Bc[k];
                        const double f1 = (double)Arf[k + 1] - (double)Bc[k + 1];
                        const double f2 = (double)Arf[k + 2] - (double)Bc[k + 2];
                        const double f3 = (double)Arf[k + 3] - (double)Bc[k + 3];
                        q0 = fma(f0, f0, q0);
                        q1 = fma(f1, f1, q1);
                        q2 = fma(f2, f2, q2);
                        q3 = fma(f3, f3, q3);
                    }
                    const double dsum = ((q0 + q1) + q2) + q3;
                    if (dsum < d1 || (dsum == d1 && code < di)) { d1 = dsum; di = code; }
                }
                #pragma unroll
                for (int off = 16; off; off >>= 1) {
                    const double ov = __shfl_xor_sync(0xffffffffu, d1, off);
                    const int    oi = __shfl_xor_sync(0xffffffffu, di, off);
                    if (ov < d1 || (ov == d1 && oi < di)) { d1 = ov; di = oi; }
                }
                if (lane == 0) {
                    sIdx[row] = di;
                    sIdxAll[row * 8 + s] = (float)di;
                }
            }
        }
        __syncthreads();

        // ---- residual update + loss (exact fp32 codebook from global/L2) ----
        {
            const int row = 4 * w + r8;
            const int idx = sIdx[row];
            #pragma unroll
            for (int j = 0; j < 4; ++j) {
                const int k = j * 32 + f * 4;
                float4 rv = *(const float4*)(A + row * LDA + k);
                const float4 cv = *(const float4*)(cbS + idx * D + k);
                rv.x -= cv.x; rv.y -= cv.y; rv.z -= cv.z; rv.w -= cv.w;
                *(float4*)(A + row * LDA + k) = rv;
                lsum += rv.x * rv.x + rv.y * rv.y + rv.z * rv.z + rv.w * rv.w;
            }
        }

        // ---- complete prefetch, recompute cnorm for stage s+1 ----
        if (s + 1 < S) {
            asm volatile("cp.async.wait_group 0;" ::: "memory");
            __syncthreads();         // B fully written, update done everywhere
            #pragma unroll
            for (int i = 0; i < 2; ++i) {
                const int code = 8 * w + 4 * i + r8;
                float psum = 0.f;
                #pragma unroll
                for (int j = 0; j < 4; ++j) {
                    const int k = j * 32 + f * 4;
                    const float4 v = *(const float4*)(B + code * LDA + k);
                    psum += v.x * v.x + v.y * v.y + v.z * v.z + v.w * v.w;
                }
                psum += __shfl_down_sync(0xffffffffu, psum, 4);
                psum += __shfl_down_sync(0xffffffffu, psum, 2);
                psum += __shfl_down_sync(0xffffffffu, psum, 1);
                if (f == 0) cnorm[code] = psum;
            }
        }
    }
    __syncthreads();

    // ---- x_q = x - final residual ----
    {
        const int row = 4 * w + r8;
        #pragma unroll
        for (int j = 0; j < 4; ++j) {
            const int k = j * 32 + f * 4;
            const float4 xv = *(const float4*)(x + (rowBase + row) * D + k);
            const float4 rv = *(const float4*)(A + row * LDA + k);
            float4 o;
            o.x = xv.x - rv.x; o.y = xv.y - rv.y;
            o.z = xv.z - rv.z; o.w = xv.w - rv.w;
            *(float4*)(out + (rowBase + row) * D + k) = o;
        }
    }

    // ---- indices (float) ----
    float* oIdx = out + (size_t)N * D + 1;
    for (int e = tid; e < ROWS * S; e += THREADS) {
        const int row = e / S, st = e % S;
        oIdx[(rowBase + row) * S + st] = sIdxAll[row * 8 + st];
    }

    // ---- per-CTA loss partial + last-CTA deterministic reduce ----
    #pragma unroll
    for (int off = 16; off; off >>= 1)
        lsum += __shfl_down_sync(0xffffffffu, lsum, off);
    if (lane == 0) sRed[w] = lsum;
    __syncthreads();
    if (tid == 0) {
        float tt = 0.f;
        #pragma unroll
        for (int i = 0; i < NWARP; ++i) tt += sRed[i];
        g_part[blockIdx.x] = tt;
        __threadfence();
        const unsigned ticket = atomicAdd(&g_cnt, 1u);
        sLast = (ticket == (unsigned)gridDim.x - 1u) ? 1 : 0;
    }
    __syncthreads();

    if (sLast) {
        __threadfence();
        const int nPart = gridDim.x;
        float ssum = 0.f;
        for (int i = tid; i < nPart; i += THREADS) ssum += g_part[i];
        #pragma unroll
        for (int off = 16; off; off >>= 1)
            ssum += __shfl_down_sync(0xffffffffu, ssum, off);
        if (lane == 0) sRed[w] = ssum;
        __syncthreads();
        if (tid == 0) {
            float tt = 0.f;
            #pragma unroll
            for (int i = 0; i < NWARP; ++i) tt += sRed[i];
            const float scale = 2.f / ((float)S * (float)N * (float)D);
            out[(size_t)N * D] = tt * scale;
            g_cnt = 0;                   // reset for next graph replay
        }
    }
}

extern "C" void kernel_launch(void* const* d_in, const int* in_sizes, int n_in,
                              void* d_out, int out_size)
{
    const float* x   = (const float*)d_in[0];
    const float* cbs = (const float*)d_in[1];
    float* out = (float*)d_out;

    const int N = in_sizes[0] / D;              // 262144
    const int S = in_sizes[1] / (C * D);        // 4
    const int nBlocks = N / ROWS;               // 2048

    cudaFuncSetAttribute(rvq_kernel, cudaFuncAttributeMaxDynamicSharedMemorySize,
                         SMEM_BYTES);
    rvq_kernel<<<nBlocks, THREADS, SMEM_BYTES>>>(x, cbs, out, N, S);
}